// round 6
// baseline (speedup 1.0000x reference)
#include <cuda_runtime.h>
#include <cuda_bf16.h>

// Problem constants
#define B_SZ   2
#define L_SZ   4096
#define DIN    512
#define H_SZ   8
#define DK     64
#define DV     64
#define DOUT   512
#define HK     (H_SZ * DK)        // 512
#define QKVC   (3 * HK)           // 1536 columns of fused QKV
#define NCHUNK 16                 // L chunks for K^T V reduction
#define LCHUNK (L_SZ / NCHUNK)    // 256

// -------- scratch (static device globals; no allocations allowed) ----------
__device__ float g_Wpack[DIN * QKVC];                       // 512 x 1536
__device__ float g_QKV[(long)B_SZ * L_SZ * QKVC];           // 8192 x 1536
__device__ float g_Mpart[B_SZ * H_SZ * NCHUNK * DK * DV];   // partial K^T V
__device__ float g_P[B_SZ * HK * DOUT];                     // per-batch 512x512

// ---- cp.async helpers (LDGSTS on sm_103a) ---------------------------------
__device__ __forceinline__ void cp_async16(void* smem_dst, const void* gmem_src) {
    unsigned saddr = (unsigned)__cvta_generic_to_shared(smem_dst);
    asm volatile("cp.async.ca.shared.global [%0], [%1], 16;\n"
                 :: "r"(saddr), "l"(gmem_src));
}
__device__ __forceinline__ void cp_async_commit() {
    asm volatile("cp.async.commit_group;\n" ::: "memory");
}
__device__ __forceinline__ void cp_async_wait_all() {
    asm volatile("cp.async.wait_group 0;\n" ::: "memory");
}

// ---------------------------------------------------------------------------
// Pack W_q|W_k|W_v (h,j,k) -> Wpack (j, [q|k|v] h*64+k)
__global__ void pack_w_kernel(const float* __restrict__ Wq,
                              const float* __restrict__ Wk,
                              const float* __restrict__ Wv) {
    int idx = blockIdx.x * blockDim.x + threadIdx.x;   // over 512*512
    if (idx >= DIN * HK) return;
    int j  = idx / HK;
    int hk = idx % HK;
    int h  = hk >> 6;
    int k  = hk & 63;
    long src = ((long)h * DIN + j) * DK + k;
    g_Wpack[(long)j * QKVC + hk]            = Wq[src];
    g_Wpack[(long)j * QKVC + HK + hk]       = Wk[src];
    g_Wpack[(long)j * QKVC + 2 * HK + hk]   = Wv[src];
}

// ---------------------------------------------------------------------------
// Tiled SGEMM: C = A(MxK) * B(KxN), row-major, batched via blockIdx.z.
// BM=BN=128, BK=8, 256 threads, 8x8 per thread.
// Double-buffered smem. B-tile prefetch via cp.async; A-tile register-staged
// (needs transpose). Loop peeled: branch-free steady state, one barrier/tile.
__global__ __launch_bounds__(256, 2)
void sgemm_kernel(const float* __restrict__ A, const float* __restrict__ B,
                  float* __restrict__ C,
                  int K, int lda, int ldb, int ldc,
                  long strideA, long strideB, long strideC) {
    A += blockIdx.z * strideA;
    B += blockIdx.z * strideB;
    C += blockIdx.z * strideC;

    __shared__ float As[2][8][128];
    __shared__ float Bs[2][8][128];

    const int tid  = threadIdx.x;
    const int brow = blockIdx.y * 128;
    const int bcol = blockIdx.x * 128;

    // A tile load map: 128 rows x 8 cols, one float4 per thread
    const int arow = tid >> 1;
    const int acol = (tid & 1) * 4;
    // B tile load map: 8 rows x 128 cols, one float4 per thread
    const int brb = tid >> 5;
    const int bcb = (tid & 31) * 4;

    const int ty = tid >> 4;   // 0..15
    const int tx = tid & 15;   // 0..15

    const float* Aptr = &A[(long)(brow + arow) * lda + acol];
    const float* Bptr = &B[(long)brb * ldb + bcol + bcb];

    float acc[8][8];
#pragma unroll
    for (int i = 0; i < 8; i++)
#pragma unroll
        for (int j = 0; j < 8; j++) acc[i][j] = 0.f;

    // Prologue: tile 0 into buffer 0. B via cp.async, A via registers.
    cp_async16(&Bs[0][brb][bcb], Bptr);
    cp_async_commit();
    {
        float4 av = *(const float4*)Aptr;
        As[0][acol + 0][arow] = av.x;
        As[0][acol + 1][arow] = av.y;
        As[0][acol + 2][arow] = av.z;
        As[0][acol + 3][arow] = av.w;
    }
    cp_async_wait_all();
    __syncthreads();

    int buf = 0;
    // Steady state: all tiles except the last. Branch-free body.
    // unroll 1: keep exactly one prefetch pair in flight (bounded MLP_p1,
    // small I-cache footprint); the body is latency-hidden by construction.
#pragma unroll 1
    for (int k0 = 8; k0 < K; k0 += 8) {
        const int nb = buf ^ 1;
        // Prefetch next tile: B fire-and-forget, A staged in registers.
        cp_async16(&Bs[nb][brb][bcb], Bptr + (long)k0 * ldb);
        cp_async_commit();
        float4 av = *(const float4*)(Aptr + k0);

#pragma unroll
        for (int kk = 0; kk < 8; kk++) {
            float ar[8], br[8];
#pragma unroll
            for (int i = 0; i < 8; i++) ar[i] = As[buf][kk][ty * 8 + i];
#pragma unroll
            for (int j = 0; j < 8; j++) br[j] = Bs[buf][kk][tx * 8 + j];
#pragma unroll
            for (int i = 0; i < 8; i++)
#pragma unroll
                for (int j = 0; j < 8; j++) acc[i][j] += ar[i] * br[j];
        }

        As[nb][acol + 0][arow] = av.x;
        As[nb][acol + 1][arow] = av.y;
        As[nb][acol + 2][arow] = av.z;
        As[nb][acol + 3][arow] = av.w;
        cp_async_wait_all();
        __syncthreads();
        buf = nb;
    }

    // Epilogue: compute the final resident tile (no prefetch).
#pragma unroll
    for (int kk = 0; kk < 8; kk++) {
        float ar[8], br[8];
#pragma unroll
        for (int i = 0; i < 8; i++) ar[i] = As[buf][kk][ty * 8 + i];
#pragma unroll
        for (int j = 0; j < 8; j++) br[j] = Bs[buf][kk][tx * 8 + j];
#pragma unroll
        for (int i = 0; i < 8; i++)
#pragma unroll
            for (int j = 0; j < 8; j++) acc[i][j] += ar[i] * br[j];
    }

#pragma unroll
    for (int i = 0; i < 8; i++) {
        float* cp = &C[(long)(brow + ty * 8 + i) * ldc + bcol + tx * 8];
        *(float4*)(cp + 0) = make_float4(acc[i][0], acc[i][1], acc[i][2], acc[i][3]);
        *(float4*)(cp + 4) = make_float4(acc[i][4], acc[i][5], acc[i][6], acc[i][7]);
    }
}

// ---------------------------------------------------------------------------
// Partial M = K^T V over an L-chunk. Grid: (chunk, h, b). 256 threads,
// each owns a 4x4 sub-tile of the 64x64 output. Deterministic (no atomics).
__global__ __launch_bounds__(256)
void ktv_partial_kernel() {
    const int chunk = blockIdx.x;
    const int h     = blockIdx.y;
    const int b     = blockIdx.z;

    __shared__ float Ks[8][64];
    __shared__ float Vs[8][64];

    const int tid = threadIdx.x;
    const int k0  = (tid >> 4) * 4;   // row group in M
    const int v0  = (tid & 15) * 4;   // col group in M

    float acc[4][4];
#pragma unroll
    for (int i = 0; i < 4; i++)
#pragma unroll
        for (int j = 0; j < 4; j++) acc[i][j] = 0.f;

    const long rowBase = (long)b * L_SZ + (long)chunk * LCHUNK;
    const float* Kcol = g_QKV + HK + h * DK;         // K section
    const float* Vcol = g_QKV + 2 * HK + h * DK;     // V section

#pragma unroll 1
    for (int it = 0; it < LCHUNK / 8; it++) {
        const int l0 = it * 8;
#pragma unroll
        for (int j = 0; j < 2; j++) {
            int idx = tid + j * 256;
            int lr  = idx >> 6;
            int col = idx & 63;
            long off = (rowBase + l0 + lr) * QKVC + col;
            Ks[lr][col] = Kcol[off];
            Vs[lr][col] = Vcol[off];
        }
        __syncthreads();
#pragma unroll
        for (int l = 0; l < 8; l++) {
            float kr[4], vr[4];
#pragma unroll
            for (int i = 0; i < 4; i++) kr[i] = Ks[l][k0 + i];
#pragma unroll
            for (int j = 0; j < 4; j++) vr[j] = Vs[l][v0 + j];
#pragma unroll
            for (int i = 0; i < 4; i++)
#pragma unroll
                for (int j = 0; j < 4; j++) acc[i][j] += kr[i] * vr[j];
        }
        __syncthreads();
    }

    float* out = g_Mpart + (((long)(b * H_SZ + h) * NCHUNK + chunk) * (DK * DV));
#pragma unroll
    for (int i = 0; i < 4; i++)
#pragma unroll
        for (int j = 0; j < 4; j++)
            out[(k0 + i) * DV + (v0 + j)] = acc[i][j];
}

// ---------------------------------------------------------------------------
// P[b][(h,k)][o] = sum_v (sum_chunks Mpart)[k][v] * W_o[h][v][o]
// Grid: (h, b), 256 threads.
__global__ __launch_bounds__(256)
void make_p_kernel(const float* __restrict__ Wo) {
    const int h = blockIdx.x;
    const int b = blockIdx.y;

    __shared__ float Ms[DK * DV];   // 16 KB

    const int tid = threadIdx.x;
    const float* mp = g_Mpart + (long)(b * H_SZ + h) * NCHUNK * (DK * DV);

    for (int idx = tid; idx < DK * DV; idx += 256) {
        float s = 0.f;
#pragma unroll
        for (int c = 0; c < NCHUNK; c++) s += mp[(long)c * (DK * DV) + idx];
        Ms[idx] = s;
    }
    __syncthreads();

    const float* wo = Wo + (long)h * DV * DOUT;
    float* pout = g_P + (long)(b * H_SZ + h) * DK * DOUT;

    for (int idx = tid; idx < DK * DOUT; idx += 256) {
        int k = idx >> 9;        // /512
        int o = idx & 511;
        float s = 0.f;
#pragma unroll
        for (int v = 0; v < DV; v++) s += Ms[k * DV + v] * wo[(long)v * DOUT + o];
        pout[idx] = s;
    }
}

// ---------------------------------------------------------------------------
extern "C" void kernel_launch(void* const* d_in, const int* in_sizes, int n_in,
                              void* d_out, int out_size) {
    (void)in_sizes; (void)n_in; (void)out_size;
    const float* x  = (const float*)d_in[0];
    const float* Wq = (const float*)d_in[1];
    const float* Wk = (const float*)d_in[2];
    const float* Wv = (const float*)d_in[3];
    const float* Wo = (const float*)d_in[4];
    float* out = (float*)d_out;

    float *pWpack, *pQKV, *pP;
    cudaGetSymbolAddress((void**)&pWpack, g_Wpack);
    cudaGetSymbolAddress((void**)&pQKV,   g_QKV);
    cudaGetSymbolAddress((void**)&pP,     g_P);

    // 1. pack projection weights
    pack_w_kernel<<<(DIN * HK + 255) / 256, 256>>>(Wq, Wk, Wv);

    // 2. QKV = x @ Wpack : (8192 x 1536 x 512)
    {
        dim3 grid(QKVC / 128, (B_SZ * L_SZ) / 128, 1);
        sgemm_kernel<<<grid, 256>>>(x, pWpack, pQKV,
                                    DIN, DIN, QKVC, QKVC, 0, 0, 0);
    }

    // 3. partial K^T V per (b,h,chunk)
    {
        dim3 grid(NCHUNK, H_SZ, B_SZ);
        ktv_partial_kernel<<<grid, 256>>>();
    }

    // 4. P = M @ W_o per (b,h)
    {
        dim3 grid(H_SZ, B_SZ);
        make_p_kernel<<<grid, 256>>>(Wo);
    }

    // 5. out[b] = Q[b] @ P[b] : (4096 x 512 x 512) x B
    {
        dim3 grid(DOUT / 128, L_SZ / 128, B_SZ);
        sgemm_kernel<<<grid, 256>>>(pQKV, pP, out,
                                    HK, QKVC, DOUT, DOUT,
                                    (long)L_SZ * QKVC,
                                    (long)HK * DOUT,
                                    (long)L_SZ * DOUT);
    }
}